// round 2
// baseline (speedup 1.0000x reference)
#include <cuda_runtime.h>
#include <math.h>

#define NN 100000
#define NE 1200000
#define DH 64
#define NG 128
#define SCAN_CHUNK 1024
#define NCHUNK 98            // ceil(NN / SCAN_CHUNK)
#define GEMM_SMEM (16896 * 4)  // sWr(4096)+sWs(4096)+sAt(64*68)+sXt(64*68) floats

// -------- scratch (static device allocations; no cudaMalloc anywhere) --------
__device__ int   g_deg[NN];
__device__ int   g_chunksum[NCHUNK];
__device__ int   g_chunkoff[NCHUNK];
__device__ int   g_rowptr[NN + 1];
__device__ int   g_cursor[NN];
__device__ int   g_esrc[NE];
__device__ float g_agg[(size_t)NN * DH];
__device__ float g_hA[(size_t)NN * DH];
__device__ float g_hB[(size_t)NN * DH];
__device__ float g_pool[NG * DH];

// ---------------- CSR build: counting sort of edges by dst ----------------
__global__ void k_zero_deg() {
    int i = blockIdx.x * blockDim.x + threadIdx.x;
    if (i < NN) g_deg[i] = 0;
}

__global__ void k_hist(const int* __restrict__ dst) {
    int e = blockIdx.x * blockDim.x + threadIdx.x;
    if (e < NE) atomicAdd(&g_deg[dst[e]], 1);
}

__global__ void k_chunksum() {
    __shared__ int red[256];
    int b = blockIdx.x, t = threadIdx.x;
    int base = b * SCAN_CHUNK;
    int s = 0;
    for (int i = t; i < SCAN_CHUNK; i += 256) {
        int idx = base + i;
        if (idx < NN) s += g_deg[idx];
    }
    red[t] = s;
    __syncthreads();
    for (int o = 128; o > 0; o >>= 1) {
        if (t < o) red[t] += red[t + o];
        __syncthreads();
    }
    if (t == 0) g_chunksum[b] = red[0];
}

__global__ void k_chunkscan() {
    __shared__ int s[NCHUNK];
    int t = threadIdx.x;
    if (t < NCHUNK) s[t] = g_chunksum[t];
    __syncthreads();
    if (t == 0) {
        int run = 0;
        for (int b = 0; b < NCHUNK; b++) { int v = s[b]; s[b] = run; run += v; }
        g_rowptr[NN] = run;  // == NE
    }
    __syncthreads();
    if (t < NCHUNK) g_chunkoff[t] = s[t];
}

__global__ void k_rowptr() {
    __shared__ int s[SCAN_CHUNK];
    int b = blockIdx.x, t = threadIdx.x;
    int idx = b * SCAN_CHUNK + t;
    int d = (idx < NN) ? g_deg[idx] : 0;
    s[t] = d;
    __syncthreads();
    // Hillis-Steele inclusive scan over 1024 elements
    for (int off = 1; off < SCAN_CHUNK; off <<= 1) {
        int v = (t >= off) ? s[t - off] : 0;
        __syncthreads();
        s[t] += v;
        __syncthreads();
    }
    if (idx < NN) {
        int excl = s[t] - d + g_chunkoff[b];
        g_rowptr[idx] = excl;
        g_cursor[idx] = excl;
    }
}

__global__ void k_scatter(const int* __restrict__ src, const int* __restrict__ dst) {
    int e = blockIdx.x * blockDim.x + threadIdx.x;
    if (e < NE) {
        int p = atomicAdd(&g_cursor[dst[e]], 1);
        g_esrc[p] = src[e];
    }
}

// ---------------- neighbor aggregation (atomic-free, CSR) ----------------
// 16 threads per node, each owns one float4 chunk of the 64-float row.
__global__ void k_agg(const float* __restrict__ in) {
    int t = threadIdx.x;
    int n = blockIdx.x * 16 + (t >> 4);
    int c = (t & 15) * 4;
    if (n >= NN) return;
    int rb = g_rowptr[n], re = g_rowptr[n + 1];
    float4 acc = make_float4(0.f, 0.f, 0.f, 0.f);
    int s = (rb < re) ? g_esrc[rb] : 0;
    for (int j = rb; j < re; j++) {
        int snext = (j + 1 < re) ? g_esrc[j + 1] : 0;  // prefetch next index
        const float4 v = *(const float4*)(in + (size_t)s * DH + c);
        acc.x += v.x; acc.y += v.y; acc.z += v.z; acc.w += v.w;
        s = snext;
    }
    *(float4*)(g_agg + (size_t)n * DH + c) = acc;
}

// ------------- fused transform: out = relu(agg@Wr + x@Ws + br) -------------
// 64 nodes x 64 cols per block, 4x4 register tile per thread.
// A tiles staged TRANSPOSED (stride 68) so inner-loop A reads are LDS.128.
__global__ void k_gemm(const float* __restrict__ Aagg, const float* __restrict__ Ax,
                       const float* __restrict__ Wr,   const float* __restrict__ Ws,
                       const float* __restrict__ br,   float* __restrict__ out) {
    extern __shared__ float sm[];
    float* sWr = sm;                    // [64][64]
    float* sWs = sm + 4096;             // [64][64]
    float* sAt = sm + 8192;             // [64 k][68] (64 nodes used)
    float* sXt = sm + 8192 + 64 * 68;   // [64 k][68]
    int t = threadIdx.x;
    int n0g = blockIdx.x * 64;

    for (int idx = t; idx < 4096; idx += 256) {
        sWr[idx] = Wr[idx];
        sWs[idx] = Ws[idx];
    }
    for (int idx = t; idx < 4096; idx += 256) {
        int r = idx >> 6, k = idx & 63;
        int n = n0g + r;
        float va = 0.f, vx = 0.f;
        if (n < NN) {
            va = Aagg[(size_t)n * 64 + k];
            vx = Ax[(size_t)n * 64 + k];
        }
        sAt[k * 68 + r] = va;
        sXt[k * 68 + r] = vx;
    }
    __syncthreads();

    int c0 = (t & 15) * 4;
    int n0 = (t >> 4) * 4;
    float acc[16];
#pragma unroll
    for (int i = 0; i < 16; i++) acc[i] = 0.f;

#pragma unroll 8
    for (int k = 0; k < 64; k++) {
        float4 wr = *(const float4*)(sWr + k * 64 + c0);
        float4 ws = *(const float4*)(sWs + k * 64 + c0);
        float4 av = *(const float4*)(sAt + k * 68 + n0);
        float4 xv = *(const float4*)(sXt + k * 68 + n0);
        float a[4]  = {av.x, av.y, av.z, av.w};
        float xx[4] = {xv.x, xv.y, xv.z, xv.w};
        float w1[4] = {wr.x, wr.y, wr.z, wr.w};
        float w2[4] = {ws.x, ws.y, ws.z, ws.w};
#pragma unroll
        for (int i = 0; i < 4; i++)
#pragma unroll
            for (int j = 0; j < 4; j++)
                acc[i * 4 + j] += a[i] * w1[j] + xx[i] * w2[j];
    }

    float b0 = br[c0], b1 = br[c0 + 1], b2 = br[c0 + 2], b3 = br[c0 + 3];
#pragma unroll
    for (int i = 0; i < 4; i++) {
        int n = n0g + n0 + i;
        if (n < NN) {
            float4 o;
            o.x = fmaxf(acc[i * 4 + 0] + b0, 0.f);
            o.y = fmaxf(acc[i * 4 + 1] + b1, 0.f);
            o.z = fmaxf(acc[i * 4 + 2] + b2, 0.f);
            o.w = fmaxf(acc[i * 4 + 3] + b3, 0.f);
            *(float4*)(out + (size_t)n * 64 + c0) = o;
        }
    }
}

// ---------------- global add pool (batch is sorted -> ranges) ----------------
__device__ __forceinline__ int lower_bound_i(const int* __restrict__ a, int n, int v) {
    int lo = 0, hi = n;
    while (lo < hi) {
        int mid = (lo + hi) >> 1;
        if (a[mid] < v) lo = mid + 1; else hi = mid;
    }
    return lo;
}

__global__ void k_pool(const float* __restrict__ h, const int* __restrict__ batch) {
    __shared__ float red[256];
    int g = blockIdx.x, t = threadIdx.x;
    int c = t & 63, q = t >> 6;
    int start = lower_bound_i(batch, NN, g);
    int end   = lower_bound_i(batch, NN, g + 1);
    float acc = 0.f;
    for (int n = start + q; n < end; n += 4) acc += h[(size_t)n * 64 + c];
    red[t] = acc;
    __syncthreads();
    if (q == 0)
        g_pool[g * 64 + c] = red[c] + red[c + 64] + red[c + 128] + red[c + 192];
}

// ---------------- FC head + log_softmax ----------------
__global__ void k_fc(const float* __restrict__ W1, const float* __restrict__ b1,
                     const float* __restrict__ W2, const float* __restrict__ b2,
                     float* __restrict__ out) {
    __shared__ float sg[64], sh[64], sl[3];
    int g = blockIdx.x, t = threadIdx.x;
    sg[t] = g_pool[g * 64 + t];
    __syncthreads();
    float a = b1[t];
#pragma unroll 8
    for (int k = 0; k < 64; k++) a += sg[k] * W1[k * 64 + t];
    sh[t] = fmaxf(a, 0.f);
    __syncthreads();
    if (t < 3) {
        float l = b2[t];
        for (int k = 0; k < 64; k++) l += sh[k] * W2[k * 3 + t];
        sl[t] = l;
    }
    __syncthreads();
    if (t < 3) {
        float m = fmaxf(sl[0], fmaxf(sl[1], sl[2]));
        float s = expf(sl[0] - m) + expf(sl[1] - m) + expf(sl[2] - m);
        out[g * 3 + t] = sl[t] - m - logf(s);
    }
}

// ------------------------------- launcher -------------------------------
extern "C" void kernel_launch(void* const* d_in, const int* in_sizes, int n_in,
                              void* d_out, int out_size) {
    const float* x     = (const float*)d_in[0];
    const int*   ei    = (const int*)d_in[1];
    const int*   src   = ei;
    const int*   dst   = ei + NE;
    const int*   batch = (const int*)d_in[2];
    const float* Wr1 = (const float*)d_in[3];
    const float* br1 = (const float*)d_in[4];
    const float* Ws1 = (const float*)d_in[5];
    const float* Wr2 = (const float*)d_in[6];
    const float* br2 = (const float*)d_in[7];
    const float* Ws2 = (const float*)d_in[8];
    const float* Wr3 = (const float*)d_in[9];
    const float* br3 = (const float*)d_in[10];
    const float* Ws3 = (const float*)d_in[11];
    const float* Wf1 = (const float*)d_in[12];
    const float* bf1 = (const float*)d_in[13];
    const float* Wf2 = (const float*)d_in[14];
    const float* bf2 = (const float*)d_in[15];
    float* out = (float*)d_out;

    cudaFuncSetAttribute(k_gemm, cudaFuncAttributeMaxDynamicSharedMemorySize, GEMM_SMEM);

    float *agg, *hA, *hB;
    cudaGetSymbolAddress((void**)&agg, g_agg);
    cudaGetSymbolAddress((void**)&hA,  g_hA);
    cudaGetSymbolAddress((void**)&hB,  g_hB);

    // CSR build (counting sort by dst)
    k_zero_deg<<<(NN + 255) / 256, 256>>>();
    k_hist<<<(NE + 255) / 256, 256>>>(dst);
    k_chunksum<<<NCHUNK, 256>>>();
    k_chunkscan<<<1, 128>>>();
    k_rowptr<<<NCHUNK, SCAN_CHUNK>>>();
    k_scatter<<<(NE + 255) / 256, 256>>>(src, dst);

    const int AGG_GRID  = (NN + 15) / 16;
    const int GEMM_GRID = (NN + 63) / 64;

    // layer 1
    k_agg<<<AGG_GRID, 256>>>(x);
    k_gemm<<<GEMM_GRID, 256, GEMM_SMEM>>>(agg, x, Wr1, Ws1, br1, hA);
    // layer 2
    k_agg<<<AGG_GRID, 256>>>(hA);
    k_gemm<<<GEMM_GRID, 256, GEMM_SMEM>>>(agg, hA, Wr2, Ws2, br2, hB);
    // layer 3
    k_agg<<<AGG_GRID, 256>>>(hB);
    k_gemm<<<GEMM_GRID, 256, GEMM_SMEM>>>(agg, hB, Wr3, Ws3, br3, hA);

    // pool + head
    k_pool<<<NG, 256>>>(hA, batch);
    k_fc<<<NG, 64>>>(Wf1, bf1, Wf2, bf2, out);
}

// round 3
// speedup vs baseline: 1.0236x; 1.0236x over previous
#include <cuda_runtime.h>
#include <math.h>

#define NN 100000
#define NE 1200000
#define DH 64
#define NG 128
#define SCAN_CHUNK 1024
#define NCHUNK 98            // ceil(NN / SCAN_CHUNK)

// GEMM smem: sWr_dup(8192) + sWs_dup(8192) + sAt(64*132) + sXt(64*132) floats
#define GEMM_SMEM ((8192 + 8192 + 8448 + 8448) * 4)

// packed f32x2 FMA: d.lo += a.lo*b.lo ; d.hi += a.hi*b.hi  (ptxas never emits; PTX only)
#define FMA2(d, a, b) asm("fma.rn.f32x2 %0, %1, %2, %0;" : "+l"(d) : "l"(a), "l"(b))
#define UNPK(lo, hi, in) asm("mov.b64 {%0, %1}, %2;" : "=f"(lo), "=f"(hi) : "l"(in))

// -------- scratch (static device allocations; no cudaMalloc anywhere) --------
__device__ int   g_deg[NN];
__device__ int   g_chunksum[NCHUNK];
__device__ int   g_chunkoff[NCHUNK];
__device__ int   g_rowptr[NN + 1];
__device__ int   g_cursor[NN];
__device__ int   g_esrc[NE];
__device__ float g_agg[(size_t)NN * DH];
__device__ float g_hA[(size_t)NN * DH];
__device__ float g_hB[(size_t)NN * DH];
__device__ float g_pool[NG * DH];

// ---------------- CSR build: counting sort of edges by dst ----------------
__global__ void k_zero_deg() {
    int i = blockIdx.x * blockDim.x + threadIdx.x;
    if (i < NN) g_deg[i] = 0;
}

__global__ void k_hist(const int* __restrict__ dst) {
    int e = blockIdx.x * blockDim.x + threadIdx.x;
    if (e < NE) atomicAdd(&g_deg[dst[e]], 1);
}

__global__ void k_chunksum() {
    __shared__ int red[256];
    int b = blockIdx.x, t = threadIdx.x;
    int base = b * SCAN_CHUNK;
    int s = 0;
    for (int i = t; i < SCAN_CHUNK; i += 256) {
        int idx = base + i;
        if (idx < NN) s += g_deg[idx];
    }
    red[t] = s;
    __syncthreads();
    for (int o = 128; o > 0; o >>= 1) {
        if (t < o) red[t] += red[t + o];
        __syncthreads();
    }
    if (t == 0) g_chunksum[b] = red[0];
}

// parallel Hillis-Steele scan over the 98 chunk sums (was serial 98-iter loop)
__global__ void k_chunkscan() {
    __shared__ int s[128];
    int t = threadIdx.x;
    int v = (t < NCHUNK) ? g_chunksum[t] : 0;
    s[t] = v;
    __syncthreads();
#pragma unroll
    for (int off = 1; off < 128; off <<= 1) {
        int u = (t >= off) ? s[t - off] : 0;
        __syncthreads();
        s[t] += u;
        __syncthreads();
    }
    if (t < NCHUNK) g_chunkoff[t] = s[t] - v;   // exclusive prefix
    if (t == NCHUNK - 1) g_rowptr[NN] = s[t];   // == NE
}

__global__ void k_rowptr() {
    __shared__ int s[SCAN_CHUNK];
    int b = blockIdx.x, t = threadIdx.x;
    int idx = b * SCAN_CHUNK + t;
    int d = (idx < NN) ? g_deg[idx] : 0;
    s[t] = d;
    __syncthreads();
    for (int off = 1; off < SCAN_CHUNK; off <<= 1) {
        int v = (t >= off) ? s[t - off] : 0;
        __syncthreads();
        s[t] += v;
        __syncthreads();
    }
    if (idx < NN) {
        int excl = s[t] - d + g_chunkoff[b];
        g_rowptr[idx] = excl;
        g_cursor[idx] = excl;
    }
}

__global__ void k_scatter(const int* __restrict__ src, const int* __restrict__ dst) {
    int e = blockIdx.x * blockDim.x + threadIdx.x;
    if (e < NE) {
        int p = atomicAdd(&g_cursor[dst[e]], 1);
        g_esrc[p] = src[e];
    }
}

// ---------------- neighbor aggregation (atomic-free, CSR) ----------------
__global__ void k_agg(const float* __restrict__ in) {
    int t = threadIdx.x;
    int n = blockIdx.x * 16 + (t >> 4);
    int c = (t & 15) * 4;
    if (n >= NN) return;
    int rb = g_rowptr[n], re = g_rowptr[n + 1];
    float4 acc = make_float4(0.f, 0.f, 0.f, 0.f);
    int s = (rb < re) ? g_esrc[rb] : 0;
    for (int j = rb; j < re; j++) {
        int snext = (j + 1 < re) ? g_esrc[j + 1] : 0;
        const float4 v = *(const float4*)(in + (size_t)s * DH + c);
        acc.x += v.x; acc.y += v.y; acc.z += v.z; acc.w += v.w;
        s = snext;
    }
    *(float4*)(g_agg + (size_t)n * DH + c) = acc;
}

// ------------- fused transform: out = relu(agg@Wr + x@Ws + br) -------------
// Block tile: 128 nodes x 64 cols, 256 threads, 8 rows x 4 cols per thread.
// f32x2 packed FMA: accumulator pairs along ROWS (free from LDS.128 of the
// transposed A tile); W duplicated in smem so the (w,w) operand is also free.
// Per k-step/thread: 8 LDS.128 + 32 FFMA2 (zero dup MOVs) -> fma-pipe bound.
__global__ void k_gemm(const float* __restrict__ Aagg, const float* __restrict__ Ax,
                       const float* __restrict__ Wr,   const float* __restrict__ Ws,
                       const float* __restrict__ br,   float* __restrict__ out) {
    extern __shared__ float sm[];
    float* sWr = sm;                     // dup [64 k][128]
    float* sWs = sm + 8192;              // dup [64 k][128]
    float* sAt = sm + 16384;             // [64 k][132] transposed (128 rows + pad)
    float* sXt = sm + 16384 + 8448;      // [64 k][132]
    int t = threadIdx.x;
    int n0g = blockIdx.x * 128;

    // Stage W duplicated: dup[k][2c] = dup[k][2c+1] = W[k][c]
    for (int idx = t; idx < 4096; idx += 256) {
        int k = idx >> 6, c = idx & 63;
        float wr = Wr[idx], ws = Ws[idx];
        sWr[k * 128 + 2 * c] = wr; sWr[k * 128 + 2 * c + 1] = wr;
        sWs[k * 128 + 2 * c] = ws; sWs[k * 128 + 2 * c + 1] = ws;
    }
    // Stage A/X transposed: sAt[k][row]
    for (int idx = t; idx < 2048; idx += 256) {   // 128 rows x 16 float4
        int r = idx >> 4, k4 = (idx & 15) * 4;
        int n = n0g + r;
        float4 va = make_float4(0.f, 0.f, 0.f, 0.f);
        float4 vx = va;
        if (n < NN) {
            va = *(const float4*)(Aagg + (size_t)n * 64 + k4);
            vx = *(const float4*)(Ax   + (size_t)n * 64 + k4);
        }
        sAt[(k4 + 0) * 132 + r] = va.x; sAt[(k4 + 1) * 132 + r] = va.y;
        sAt[(k4 + 2) * 132 + r] = va.z; sAt[(k4 + 3) * 132 + r] = va.w;
        sXt[(k4 + 0) * 132 + r] = vx.x; sXt[(k4 + 1) * 132 + r] = vx.y;
        sXt[(k4 + 2) * 132 + r] = vx.z; sXt[(k4 + 3) * 132 + r] = vx.w;
    }
    __syncthreads();

    int q  = t & 15;          // column group: owns cols {2q, 2q+1, 32+2q, 32+2q+1}
    int n0 = (t >> 4) * 8;    // 8 consecutive rows

    // acc[rp*4 + ci]: rp = row pair 0..3 (rows n0+2rp, n0+2rp+1), ci = owned col 0..3
    unsigned long long acc[16];
#pragma unroll
    for (int i = 0; i < 16; i++) acc[i] = 0ull;

#pragma unroll 8
    for (int k = 0; k < 64; k++) {
        // dup W pairs: (w_{2q},w_{2q}),(w_{2q+1},w_{2q+1}) then the +32 cols
        ulonglong2 wrA = *(const ulonglong2*)(sWr + k * 128 + 4 * q);
        ulonglong2 wrB = *(const ulonglong2*)(sWr + k * 128 + 64 + 4 * q);
        ulonglong2 wsA = *(const ulonglong2*)(sWs + k * 128 + 4 * q);
        ulonglong2 wsB = *(const ulonglong2*)(sWs + k * 128 + 64 + 4 * q);
        // A row pairs: rows (n0,n0+1),(n0+2,n0+3) then (n0+4..n0+7)
        ulonglong2 a01 = *(const ulonglong2*)(sAt + k * 132 + n0);
        ulonglong2 a23 = *(const ulonglong2*)(sAt + k * 132 + n0 + 4);
        ulonglong2 x01 = *(const ulonglong2*)(sXt + k * 132 + n0);
        ulonglong2 x23 = *(const ulonglong2*)(sXt + k * 132 + n0 + 4);

        FMA2(acc[0],  a01.x, wrA.x); FMA2(acc[0],  x01.x, wsA.x);
        FMA2(acc[1],  a01.x, wrA.y); FMA2(acc[1],  x01.x, wsA.y);
        FMA2(acc[2],  a01.x, wrB.x); FMA2(acc[2],  x01.x, wsB.x);
        FMA2(acc[3],  a01.x, wrB.y); FMA2(acc[3],  x01.x, wsB.y);

        FMA2(acc[4],  a01.y, wrA.x); FMA2(acc[4],  x01.y, wsA.x);
        FMA2(acc[5],  a01.y, wrA.y); FMA2(acc[5],  x01.y, wsA.y);
        FMA2(acc[6],  a01.y, wrB.x); FMA2(acc[6],  x01.y, wsB.x);
        FMA2(acc[7],  a01.y, wrB.y); FMA2(acc[7],  x01.y, wsB.y);

        FMA2(acc[8],  a23.x, wrA.x); FMA2(acc[8],  x23.x, wsA.x);
        FMA2(acc[9],  a23.x, wrA.y); FMA2(acc[9],  x23.x, wsA.y);
        FMA2(acc[10], a23.x, wrB.x); FMA2(acc[10], x23.x, wsB.x);
        FMA2(acc[11], a23.x, wrB.y); FMA2(acc[11], x23.x, wsB.y);

        FMA2(acc[12], a23.y, wrA.x); FMA2(acc[12], x23.y, wsA.x);
        FMA2(acc[13], a23.y, wrA.y); FMA2(acc[13], x23.y, wsA.y);
        FMA2(acc[14], a23.y, wrB.x); FMA2(acc[14], x23.y, wsB.x);
        FMA2(acc[15], a23.y, wrB.y); FMA2(acc[15], x23.y, wsB.y);
    }

    int cA = 2 * q;        // first col pair base
    int cB = 32 + 2 * q;   // second col pair base
    float bA0 = br[cA], bA1 = br[cA + 1], bB0 = br[cB], bB1 = br[cB + 1];

#pragma unroll
    for (int rp = 0; rp < 4; rp++) {
        float vA0lo, vA0hi, vA1lo, vA1hi, vB0lo, vB0hi, vB1lo, vB1hi;
        UNPK(vA0lo, vA0hi, acc[rp * 4 + 0]);
        UNPK(vA1lo, vA1hi, acc[rp * 4 + 1]);
        UNPK(vB0lo, vB0hi, acc[rp * 4 + 2]);
        UNPK(vB1lo, vB1hi, acc[rp * 4 + 3]);
        int rlo = n0g + n0 + 2 * rp;
        if (rlo < NN) {
            float2 oA = make_float2(fmaxf(vA0lo + bA0, 0.f), fmaxf(vA1lo + bA1, 0.f));
            float2 oB = make_float2(fmaxf(vB0lo + bB0, 0.f), fmaxf(vB1lo + bB1, 0.f));
            *(float2*)(out + (size_t)rlo * 64 + cA) = oA;
            *(float2*)(out + (size_t)rlo * 64 + cB) = oB;
        }
        if (rlo + 1 < NN) {
            float2 oA = make_float2(fmaxf(vA0hi + bA0, 0.f), fmaxf(vA1hi + bA1, 0.f));
            float2 oB = make_float2(fmaxf(vB0hi + bB0, 0.f), fmaxf(vB1hi + bB1, 0.f));
            *(float2*)(out + (size_t)(rlo + 1) * 64 + cA) = oA;
            *(float2*)(out + (size_t)(rlo + 1) * 64 + cB) = oB;
        }
    }
}

// ---------------- global add pool (batch is sorted -> ranges) ----------------
__device__ __forceinline__ int lower_bound_i(const int* __restrict__ a, int n, int v) {
    int lo = 0, hi = n;
    while (lo < hi) {
        int mid = (lo + hi) >> 1;
        if (a[mid] < v) lo = mid + 1; else hi = mid;
    }
    return lo;
}

__global__ void k_pool(const float* __restrict__ h, const int* __restrict__ batch) {
    __shared__ float red[256];
    int g = blockIdx.x, t = threadIdx.x;
    int c = t & 63, q = t >> 6;
    int start = lower_bound_i(batch, NN, g);
    int end   = lower_bound_i(batch, NN, g + 1);
    float acc = 0.f;
    for (int n = start + q; n < end; n += 4) acc += h[(size_t)n * 64 + c];
    red[t] = acc;
    __syncthreads();
    if (q == 0)
        g_pool[g * 64 + c] = red[c] + red[c + 64] + red[c + 128] + red[c + 192];
}

// ---------------- FC head + log_softmax ----------------
__global__ void k_fc(const float* __restrict__ W1, const float* __restrict__ b1,
                     const float* __restrict__ W2, const float* __restrict__ b2,
                     float* __restrict__ out) {
    __shared__ float sg[64], sh[64], sl[3];
    int g = blockIdx.x, t = threadIdx.x;
    sg[t] = g_pool[g * 64 + t];
    __syncthreads();
    float a = b1[t];
#pragma unroll 8
    for (int k = 0; k < 64; k++) a += sg[k] * W1[k * 64 + t];
    sh[t] = fmaxf(a, 0.f);
    __syncthreads();
    if (t < 3) {
        float l = b2[t];
        for (int k = 0; k < 64; k++) l += sh[k] * W2[k * 3 + t];
        sl[t] = l;
    }
    __syncthreads();
    if (t < 3) {
        float m = fmaxf(sl[0], fmaxf(sl[1], sl[2]));
        float s = expf(sl[0] - m) + expf(sl[1] - m) + expf(sl[2] - m);
        out[g * 3 + t] = sl[t] - m - logf(s);
    }
}

// ------------------------------- launcher -------------------------------
extern "C" void kernel_launch(void* const* d_in, const int* in_sizes, int n_in,
                              void* d_out, int out_size) {
    const float* x     = (const float*)d_in[0];
    const int*   ei    = (const int*)d_in[1];
    const int*   src   = ei;
    const int*   dst   = ei + NE;
    const int*   batch = (const int*)d_in[2];
    const float* Wr1 = (const float*)d_in[3];
    const float* br1 = (const float*)d_in[4];
    const float* Ws1 = (const float*)d_in[5];
    const float* Wr2 = (const float*)d_in[6];
    const float* br2 = (const float*)d_in[7];
    const float* Ws2 = (const float*)d_in[8];
    const float* Wr3 = (const float*)d_in[9];
    const float* br3 = (const float*)d_in[10];
    const float* Ws3 = (const float*)d_in[11];
    const float* Wf1 = (const float*)d_in[12];
    const float* bf1 = (const float*)d_in[13];
    const float* Wf2 = (const float*)d_in[14];
    const float* bf2 = (const float*)d_in[15];
    float* out = (float*)d_out;

    cudaFuncSetAttribute(k_gemm, cudaFuncAttributeMaxDynamicSharedMemorySize, GEMM_SMEM);

    float *agg, *hA, *hB;
    cudaGetSymbolAddress((void**)&agg, g_agg);
    cudaGetSymbolAddress((void**)&hA,  g_hA);
    cudaGetSymbolAddress((void**)&hB,  g_hB);

    // CSR build (counting sort by dst)
    k_zero_deg<<<(NN + 255) / 256, 256>>>();
    k_hist<<<(NE + 255) / 256, 256>>>(dst);
    k_chunksum<<<NCHUNK, 256>>>();
    k_chunkscan<<<1, 128>>>();
    k_rowptr<<<NCHUNK, SCAN_CHUNK>>>();
    k_scatter<<<(NE + 255) / 256, 256>>>(src, dst);

    const int AGG_GRID  = (NN + 15) / 16;
    const int GEMM_GRID = (NN + 127) / 128;

    // layer 1
    k_agg<<<AGG_GRID, 256>>>(x);
    k_gemm<<<GEMM_GRID, 256, GEMM_SMEM>>>(agg, x, Wr1, Ws1, br1, hA);
    // layer 2
    k_agg<<<AGG_GRID, 256>>>(hA);
    k_gemm<<<GEMM_GRID, 256, GEMM_SMEM>>>(agg, hA, Wr2, Ws2, br2, hB);
    // layer 3
    k_agg<<<AGG_GRID, 256>>>(hB);
    k_gemm<<<GEMM_GRID, 256, GEMM_SMEM>>>(agg, hB, Wr3, Ws3, br3, hA);

    // pool + head
    k_pool<<<NG, 256>>>(hA, batch);
    k_fc<<<NG, 64>>>(Wf1, bf1, Wf2, bf2, out);
}

// round 5
// speedup vs baseline: 1.0766x; 1.0518x over previous
#include <cuda_runtime.h>
#include <math.h>

#define NN 100000
#define NE 1200000
#define DH 64
#define NG 128
#define SCAN_CHUNK 1024
#define NCHUNK 98            // ceil(NN / SCAN_CHUNK)

// fused layer smem: sWr(4096) + sWs(4096) + sAt(64*132) + sXt(64*132) floats
#define LAYER_SMEM ((4096 + 4096 + 8448 + 8448) * 4)   // 100352 B -> 2 blocks/SM

// packed f32x2 FMA: d.lo += a.lo*b.lo ; d.hi += a.hi*b.hi  (PTX-only pattern)
#define FMA2(d, a, b) asm("fma.rn.f32x2 %0, %1, %2, %0;" : "+l"(d) : "l"(a), "l"(b))
#define UNPK(lo, hi, in) asm("mov.b64 {%0, %1}, %2;" : "=f"(lo), "=f"(hi) : "l"(in))
#define PACK2(d, s) asm("mov.b64 %0, {%1, %1};" : "=l"(d) : "f"(s))

// -------- scratch (static device allocations; no cudaMalloc anywhere) --------
__device__ int   g_deg[NN];
__device__ int   g_chunksum[NCHUNK];
__device__ int   g_chunkoff[NCHUNK];
__device__ int   g_rowptr[NN + 1];
__device__ int   g_cursor[NN];
__device__ int   g_esrc[NE];
__device__ float g_hA[(size_t)NN * DH];
__device__ float g_hB[(size_t)NN * DH];
__device__ float g_pool[NG * DH];

// ---------------- CSR build: counting sort of edges by dst ----------------
__global__ void k_hist(const int* __restrict__ dst) {
    int e = blockIdx.x * blockDim.x + threadIdx.x;
    if (e < NE) atomicAdd(&g_deg[dst[e]], 1);
}

__global__ void k_chunksum() {
    __shared__ int red[256];
    int b = blockIdx.x, t = threadIdx.x;
    int base = b * SCAN_CHUNK;
    int s = 0;
    for (int i = t; i < SCAN_CHUNK; i += 256) {
        int idx = base + i;
        if (idx < NN) s += g_deg[idx];
    }
    red[t] = s;
    __syncthreads();
    for (int o = 128; o > 0; o >>= 1) {
        if (t < o) red[t] += red[t + o];
        __syncthreads();
    }
    if (t == 0) g_chunksum[b] = red[0];
}

__global__ void k_chunkscan() {
    __shared__ int s[128];
    int t = threadIdx.x;
    int v = (t < NCHUNK) ? g_chunksum[t] : 0;
    s[t] = v;
    __syncthreads();
#pragma unroll
    for (int off = 1; off < 128; off <<= 1) {
        int u = (t >= off) ? s[t - off] : 0;
        __syncthreads();
        s[t] += u;
        __syncthreads();
    }
    if (t < NCHUNK) g_chunkoff[t] = s[t] - v;
    if (t == NCHUNK - 1) g_rowptr[NN] = s[t];
}

__global__ void k_rowptr() {
    __shared__ int s[SCAN_CHUNK];
    int b = blockIdx.x, t = threadIdx.x;
    int idx = b * SCAN_CHUNK + t;
    int d = (idx < NN) ? g_deg[idx] : 0;
    s[t] = d;
    __syncthreads();
    for (int off = 1; off < SCAN_CHUNK; off <<= 1) {
        int v = (t >= off) ? s[t - off] : 0;
        __syncthreads();
        s[t] += v;
        __syncthreads();
    }
    if (idx < NN) {
        int excl = s[t] - d + g_chunkoff[b];
        g_rowptr[idx] = excl;
        g_cursor[idx] = excl;
    }
}

__global__ void k_scatter(const int* __restrict__ src, const int* __restrict__ dst) {
    int e = blockIdx.x * blockDim.x + threadIdx.x;
    if (e < NE) {
        int p = atomicAdd(&g_cursor[dst[e]], 1);
        g_esrc[p] = src[e];
    }
}

// --------- fused layer: agg = CSR-gather-sum; out = relu(agg@Wr + x@Ws + br) ---------
// Block: 128 nodes x 64 cols, 256 threads, __launch_bounds__ pins 2 blocks/SM so
// one block's L2-gather overlaps the other's fma phase.
// Mainloop: FFMA2 row-pairs; W dup'd into (w,w) pairs in registers (alu pipe, free).
__global__ void __launch_bounds__(256, 2)
k_layer(const float* __restrict__ in,
        const float* __restrict__ Wr, const float* __restrict__ Ws,
        const float* __restrict__ br, float* __restrict__ out) {
    extern __shared__ float sm[];
    float* sWr = sm;                  // [64 k][64 c]
    float* sWs = sm + 4096;           // [64 k][64 c]
    float* sAt = sm + 8192;           // [64 k][132] transposed agg (128 rows + pad)
    float* sXt = sm + 8192 + 8448;    // [64 k][132] transposed x
    int t = threadIdx.x;
    int n0g = blockIdx.x * 128;

    // stage W
    for (int idx = t; idx < 4096; idx += 256) {
        sWr[idx] = Wr[idx];
        sWs[idx] = Ws[idx];
    }
    // stage X transposed
    for (int idx = t; idx < 2048; idx += 256) {   // 128 rows x 16 float4
        int r = idx >> 4, k4 = (idx & 15) * 4;
        int n = n0g + r;
        float4 vx = make_float4(0.f, 0.f, 0.f, 0.f);
        if (n < NN) vx = *(const float4*)(in + (size_t)n * 64 + k4);
        sXt[(k4 + 0) * 132 + r] = vx.x; sXt[(k4 + 1) * 132 + r] = vx.y;
        sXt[(k4 + 2) * 132 + r] = vx.z; sXt[(k4 + 3) * 132 + r] = vx.w;
    }
    // gather-aggregate into sAt (16 threads per node, 8 node-groups)
    {
        int nloc = t >> 4;
        int c = (t & 15) * 4;
#pragma unroll
        for (int gblk = 0; gblk < 8; gblk++) {
            int r = gblk * 16 + nloc;
            int n = n0g + r;
            float4 acc = make_float4(0.f, 0.f, 0.f, 0.f);
            if (n < NN) {
                int rb = g_rowptr[n], re = g_rowptr[n + 1];
                int s = (rb < re) ? g_esrc[rb] : 0;
                for (int j = rb; j < re; j++) {
                    int snext = (j + 1 < re) ? g_esrc[j + 1] : 0;
                    const float4 v = *(const float4*)(in + (size_t)s * 64 + c);
                    acc.x += v.x; acc.y += v.y; acc.z += v.z; acc.w += v.w;
                    s = snext;
                }
            }
            sAt[(c + 0) * 132 + r] = acc.x; sAt[(c + 1) * 132 + r] = acc.y;
            sAt[(c + 2) * 132 + r] = acc.z; sAt[(c + 3) * 132 + r] = acc.w;
        }
    }
    __syncthreads();

    int q  = t & 15;          // owns cols {2q, 2q+1, 32+2q, 32+2q+1}
    int n0 = (t >> 4) * 8;    // 8 consecutive rows

    unsigned long long acc[16];
#pragma unroll
    for (int i = 0; i < 16; i++) acc[i] = 0ull;

#pragma unroll 8
    for (int k = 0; k < 64; k++) {
        float2 wrA = *(const float2*)(sWr + k * 64 + 2 * q);
        float2 wrB = *(const float2*)(sWr + k * 64 + 32 + 2 * q);
        float2 wsA = *(const float2*)(sWs + k * 64 + 2 * q);
        float2 wsB = *(const float2*)(sWs + k * 64 + 32 + 2 * q);
        unsigned long long wrA0, wrA1, wrB0, wrB1, wsA0, wsA1, wsB0, wsB1;
        PACK2(wrA0, wrA.x); PACK2(wrA1, wrA.y);
        PACK2(wrB0, wrB.x); PACK2(wrB1, wrB.y);
        PACK2(wsA0, wsA.x); PACK2(wsA1, wsA.y);
        PACK2(wsB0, wsB.x); PACK2(wsB1, wsB.y);

        ulonglong2 a01 = *(const ulonglong2*)(sAt + k * 132 + n0);
        ulonglong2 a23 = *(const ulonglong2*)(sAt + k * 132 + n0 + 4);
        ulonglong2 x01 = *(const ulonglong2*)(sXt + k * 132 + n0);
        ulonglong2 x23 = *(const ulonglong2*)(sXt + k * 132 + n0 + 4);

        FMA2(acc[0],  a01.x, wrA0); FMA2(acc[0],  x01.x, wsA0);
        FMA2(acc[1],  a01.x, wrA1); FMA2(acc[1],  x01.x, wsA1);
        FMA2(acc[2],  a01.x, wrB0); FMA2(acc[2],  x01.x, wsB0);
        FMA2(acc[3],  a01.x, wrB1); FMA2(acc[3],  x01.x, wsB1);

        FMA2(acc[4],  a01.y, wrA0); FMA2(acc[4],  x01.y, wsA0);
        FMA2(acc[5],  a01.y, wrA1); FMA2(acc[5],  x01.y, wsA1);
        FMA2(acc[6],  a01.y, wrB0); FMA2(acc[6],  x01.y, wsB0);
        FMA2(acc[7],  a01.y, wrB1); FMA2(acc[7],  x01.y, wsB1);

        FMA2(acc[8],  a23.x, wrA0); FMA2(acc[8],  x23.x, wsA0);
        FMA2(acc[9],  a23.x, wrA1); FMA2(acc[9],  x23.x, wsA1);
        FMA2(acc[10], a23.x, wrB0); FMA2(acc[10], x23.x, wsB0);
        FMA2(acc[11], a23.x, wrB1); FMA2(acc[11], x23.x, wsB1);

        FMA2(acc[12], a23.y, wrA0); FMA2(acc[12], x23.y, wsA0);
        FMA2(acc[13], a23.y, wrA1); FMA2(acc[13], x23.y, wsA1);
        FMA2(acc[14], a23.y, wrB0); FMA2(acc[14], x23.y, wsB0);
        FMA2(acc[15], a23.y, wrB1); FMA2(acc[15], x23.y, wsB1);
    }

    int cA = 2 * q;
    int cB = 32 + 2 * q;
    float bA0 = br[cA], bA1 = br[cA + 1], bB0 = br[cB], bB1 = br[cB + 1];

#pragma unroll
    for (int rp = 0; rp < 4; rp++) {
        float vA0lo, vA0hi, vA1lo, vA1hi, vB0lo, vB0hi, vB1lo, vB1hi;
        UNPK(vA0lo, vA0hi, acc[rp * 4 + 0]);
        UNPK(vA1lo, vA1hi, acc[rp * 4 + 1]);
        UNPK(vB0lo, vB0hi, acc[rp * 4 + 2]);
        UNPK(vB1lo, vB1hi, acc[rp * 4 + 3]);
        int rlo = n0g + n0 + 2 * rp;
        if (rlo < NN) {
            float2 oA = make_float2(fmaxf(vA0lo + bA0, 0.f), fmaxf(vA1lo + bA1, 0.f));
            float2 oB = make_float2(fmaxf(vB0lo + bB0, 0.f), fmaxf(vB1lo + bB1, 0.f));
            *(float2*)(out + (size_t)rlo * 64 + cA) = oA;
            *(float2*)(out + (size_t)rlo * 64 + cB) = oB;
        }
        if (rlo + 1 < NN) {
            float2 oA = make_float2(fmaxf(vA0hi + bA0, 0.f), fmaxf(vA1hi + bA1, 0.f));
            float2 oB = make_float2(fmaxf(vB0hi + bB0, 0.f), fmaxf(vB1hi + bB1, 0.f));
            *(float2*)(out + (size_t)(rlo + 1) * 64 + cA) = oA;
            *(float2*)(out + (size_t)(rlo + 1) * 64 + cB) = oB;
        }
    }
}

// ---------------- global add pool (batch is sorted -> ranges) ----------------
__device__ __forceinline__ int lower_bound_i(const int* __restrict__ a, int n, int v) {
    int lo = 0, hi = n;
    while (lo < hi) {
        int mid = (lo + hi) >> 1;
        if (a[mid] < v) lo = mid + 1; else hi = mid;
    }
    return lo;
}

__global__ void k_pool(const float* __restrict__ h, const int* __restrict__ batch) {
    __shared__ float red[512];
    int g = blockIdx.x, t = threadIdx.x;
    int c = t & 63, q = t >> 6;     // 8 row-lanes per column
    int start = lower_bound_i(batch, NN, g);
    int end   = lower_bound_i(batch, NN, g + 1);
    float acc = 0.f;
    for (int n = start + q; n < end; n += 8) acc += h[(size_t)n * 64 + c];
    red[t] = acc;
    __syncthreads();
    if (q < 4) red[t] += red[t + 256];
    __syncthreads();
    if (q < 2) red[t] += red[t + 128];
    __syncthreads();
    if (q == 0)
        g_pool[g * 64 + c] = red[c] + red[c + 64];
}

// ---------------- FC head + log_softmax ----------------
__global__ void k_fc(const float* __restrict__ W1, const float* __restrict__ b1,
                     const float* __restrict__ W2, const float* __restrict__ b2,
                     float* __restrict__ out) {
    __shared__ float sg[64], sh[64], sl[3];
    int g = blockIdx.x, t = threadIdx.x;
    sg[t] = g_pool[g * 64 + t];
    __syncthreads();
    float a = b1[t];
#pragma unroll 8
    for (int k = 0; k < 64; k++) a += sg[k] * W1[k * 64 + t];
    sh[t] = fmaxf(a, 0.f);
    __syncthreads();
    if (t < 3) {
        float l = b2[t];
        for (int k = 0; k < 64; k++) l += sh[k] * W2[k * 3 + t];
        sl[t] = l;
    }
    __syncthreads();
    if (t < 3) {
        float m = fmaxf(sl[0], fmaxf(sl[1], sl[2]));
        float s = expf(sl[0] - m) + expf(sl[1] - m) + expf(sl[2] - m);
        out[g * 3 + t] = sl[t] - m - logf(s);
    }
}

// ------------------------------- launcher -------------------------------
extern "C" void kernel_launch(void* const* d_in, const int* in_sizes, int n_in,
                              void* d_out, int out_size) {
    const float* x     = (const float*)d_in[0];
    const int*   ei    = (const int*)d_in[1];
    const int*   src   = ei;
    const int*   dst   = ei + NE;
    const int*   batch = (const int*)d_in[2];
    const float* Wr1 = (const float*)d_in[3];
    const float* br1 = (const float*)d_in[4];
    const float* Ws1 = (const float*)d_in[5];
    const float* Wr2 = (const float*)d_in[6];
    const float* br2 = (const float*)d_in[7];
    const float* Ws2 = (const float*)d_in[8];
    const float* Wr3 = (const float*)d_in[9];
    const float* br3 = (const float*)d_in[10];
    const float* Ws3 = (const float*)d_in[11];
    const float* Wf1 = (const float*)d_in[12];
    const float* bf1 = (const float*)d_in[13];
    const float* Wf2 = (const float*)d_in[14];
    const float* bf2 = (const float*)d_in[15];
    float* out = (float*)d_out;

    cudaFuncSetAttribute(k_layer, cudaFuncAttributeMaxDynamicSharedMemorySize, LAYER_SMEM);

    float *hA, *hB;
    int* degp;
    cudaGetSymbolAddress((void**)&hA,   g_hA);
    cudaGetSymbolAddress((void**)&hB,   g_hB);
    cudaGetSymbolAddress((void**)&degp, g_deg);

    // CSR build (counting sort by dst)
    cudaMemsetAsync(degp, 0, NN * sizeof(int));
    k_hist<<<(NE + 255) / 256, 256>>>(dst);
    k_chunksum<<<NCHUNK, 256>>>();
    k_chunkscan<<<1, 128>>>();
    k_rowptr<<<NCHUNK, SCAN_CHUNK>>>();
    k_scatter<<<(NE + 255) / 256, 256>>>(src, dst);

    const int LAYER_GRID = (NN + 127) / 128;

    k_layer<<<LAYER_GRID, 256, LAYER_SMEM>>>(x,  Wr1, Ws1, br1, hA);
    k_layer<<<LAYER_GRID, 256, LAYER_SMEM>>>(hA, Wr2, Ws2, br2, hB);
    k_layer<<<LAYER_GRID, 256, LAYER_SMEM>>>(hB, Wr3, Ws3, br3, hA);

    k_pool<<<NG, 512>>>(hA, batch);
    k_fc<<<NG, 64>>>(Wf1, bf1, Wf2, bf2, out);
}

// round 7
// speedup vs baseline: 1.1811x; 1.0971x over previous
#include <cuda_runtime.h>
#include <math.h>

#define NN 100000
#define NE 1200000
#define DH 64
#define NG 128
#define SCAN_CHUNK 1024
#define NCHUNK 98            // ceil(NN / SCAN_CHUNK)

// fused layer smem: sWr(4096) + sWs(4096) + sAt(64*132) + sXt(64*132) floats
#define LAYER_SMEM ((4096 + 4096 + 8448 + 8448) * 4)   // 100352 B -> 2 blocks/SM

// packed f32x2 FMA: d.lo += a.lo*b.lo ; d.hi += a.hi*b.hi  (PTX-only pattern)
#define FMA2(d, a, b) asm("fma.rn.f32x2 %0, %1, %2, %0;" : "+l"(d) : "l"(a), "l"(b))
#define UNPK(lo, hi, in) asm("mov.b64 {%0, %1}, %2;" : "=f"(lo), "=f"(hi) : "l"(in))
#define PACK2(d, s) asm("mov.b64 %0, {%1, %1};" : "=l"(d) : "f"(s))

// -------- scratch (static device allocations; no cudaMalloc anywhere) --------
__device__ int                g_deg[NN];
__device__ unsigned long long g_scanpkt[NCHUNK];   // (flag<<32)|value; 1=agg, 2=prefix
__device__ int                g_rowptr[NN + 1];
__device__ int                g_cursor[NN];
__device__ int                g_esrc[NE];
__device__ float              g_hA[(size_t)NN * DH];
__device__ float              g_hB[(size_t)NN * DH];
__device__ float              g_pool[NG * DH];

// ---------------- CSR build: counting sort of edges by dst ----------------
__global__ void k_hist(const int* __restrict__ dst) {
    int e = blockIdx.x * blockDim.x + threadIdx.x;
    if (e < NE) atomicAdd(&g_deg[dst[e]], 1);
}

// One-kernel exclusive scan of g_deg -> g_rowptr via decoupled lookback.
// 98 blocks all fit on 148 SMs simultaneously -> polling is deadlock-free.
__global__ void k_scan() {
    __shared__ int s[SCAN_CHUNK];
    __shared__ int s_excl;
    int b = blockIdx.x, t = threadIdx.x;
    int idx = b * SCAN_CHUNK + t;
    int d = (idx < NN) ? g_deg[idx] : 0;
    s[t] = d;
    __syncthreads();
    for (int off = 1; off < SCAN_CHUNK; off <<= 1) {
        int v = (t >= off) ? s[t - off] : 0;
        __syncthreads();
        s[t] += v;
        __syncthreads();
    }
    int total = s[SCAN_CHUNK - 1];

    if (t == 0) {
        int excl = 0;
        if (b == 0) {
            atomicExch(&g_scanpkt[0], (2ull << 32) | (unsigned)total);
        } else {
            // publish aggregate, then look back
            atomicExch(&g_scanpkt[b], (1ull << 32) | (unsigned)total);
            int run = 0;
            for (int p = b - 1; p >= 0; p--) {
                unsigned long long v;
                do { v = atomicAdd(&g_scanpkt[p], 0ull); } while ((v >> 32) == 0ull);
                run += (int)(v & 0xffffffffull);
                if ((v >> 32) == 2ull) break;
            }
            excl = run;
            atomicExch(&g_scanpkt[b], (2ull << 32) | (unsigned)(excl + total));
        }
        s_excl = excl;
        if (b == NCHUNK - 1) g_rowptr[NN] = excl + total;   // == NE
    }
    __syncthreads();
    int excl = s_excl;
    if (idx < NN) {
        int e = s[t] - d + excl;
        g_rowptr[idx] = e;
        g_cursor[idx] = e;
    }
}

__global__ void k_scatter(const int* __restrict__ src, const int* __restrict__ dst) {
    int e = blockIdx.x * blockDim.x + threadIdx.x;
    if (e < NE) {
        int p = atomicAdd(&g_cursor[dst[e]], 1);
        g_esrc[p] = src[e];
    }
}

// --------- fused layer: agg = CSR-gather-sum; out = relu(agg@Wr + x@Ws + br) ---------
// Block: 128 nodes x 64 cols, 256 threads, 2 blocks/SM.
// Gather: 4-wide index batching -> 4 independent row loads per iter (MLP>=4)
//         so the phase runs at L2 bandwidth instead of L2 latency.
// Mainloop: FFMA2 row-pairs; W dup'd into (w,w) register pairs (alu pipe).
__global__ void __launch_bounds__(256, 2)
k_layer(const float* __restrict__ in,
        const float* __restrict__ Wr, const float* __restrict__ Ws,
        const float* __restrict__ br, float* __restrict__ out) {
    extern __shared__ float sm[];
    float* sWr = sm;                  // [64 k][64 c]
    float* sWs = sm + 4096;           // [64 k][64 c]
    float* sAt = sm + 8192;           // [64 k][132] transposed agg (128 rows + pad)
    float* sXt = sm + 8192 + 8448;    // [64 k][132] transposed x
    int t = threadIdx.x;
    int n0g = blockIdx.x * 128;

    // stage W
    for (int idx = t; idx < 1024; idx += 256) {
        float4 wr = *(const float4*)(Wr + idx * 4);
        float4 ws = *(const float4*)(Ws + idx * 4);
        *(float4*)(sWr + idx * 4) = wr;
        *(float4*)(sWs + idx * 4) = ws;
    }
    // stage X transposed
    for (int idx = t; idx < 2048; idx += 256) {   // 128 rows x 16 float4
        int r = idx >> 4, k4 = (idx & 15) * 4;
        int n = n0g + r;
        float4 vx = make_float4(0.f, 0.f, 0.f, 0.f);
        if (n < NN) vx = *(const float4*)(in + (size_t)n * 64 + k4);
        sXt[(k4 + 0) * 132 + r] = vx.x; sXt[(k4 + 1) * 132 + r] = vx.y;
        sXt[(k4 + 2) * 132 + r] = vx.z; sXt[(k4 + 3) * 132 + r] = vx.w;
    }
    // gather-aggregate into sAt (16 threads per node, 8 node-groups, 4-wide MLP)
    {
        int nloc = t >> 4;
        int c = (t & 15) * 4;
#pragma unroll
        for (int gblk = 0; gblk < 8; gblk++) {
            int r = gblk * 16 + nloc;
            int n = n0g + r;
            float4 a0 = make_float4(0.f, 0.f, 0.f, 0.f);
            float4 a1 = a0;
            if (n < NN) {
                int rb = g_rowptr[n], re = g_rowptr[n + 1];
                int j = rb;
                for (; j + 4 <= re; j += 4) {
                    int s0 = g_esrc[j],     s1 = g_esrc[j + 1];
                    int s2 = g_esrc[j + 2], s3 = g_esrc[j + 3];
                    float4 v0 = *(const float4*)(in + (size_t)s0 * 64 + c);
                    float4 v1 = *(const float4*)(in + (size_t)s1 * 64 + c);
                    float4 v2 = *(const float4*)(in + (size_t)s2 * 64 + c);
                    float4 v3 = *(const float4*)(in + (size_t)s3 * 64 + c);
                    a0.x += v0.x; a0.y += v0.y; a0.z += v0.z; a0.w += v0.w;
                    a1.x += v1.x; a1.y += v1.y; a1.z += v1.z; a1.w += v1.w;
                    a0.x += v2.x; a0.y += v2.y; a0.z += v2.z; a0.w += v2.w;
                    a1.x += v3.x; a1.y += v3.y; a1.z += v3.z; a1.w += v3.w;
                }
                for (; j < re; j++) {
                    int s0 = g_esrc[j];
                    float4 v0 = *(const float4*)(in + (size_t)s0 * 64 + c);
                    a0.x += v0.x; a0.y += v0.y; a0.z += v0.z; a0.w += v0.w;
                }
            }
            sAt[(c + 0) * 132 + r] = a0.x + a1.x;
            sAt[(c + 1) * 132 + r] = a0.y + a1.y;
            sAt[(c + 2) * 132 + r] = a0.z + a1.z;
            sAt[(c + 3) * 132 + r] = a0.w + a1.w;
        }
    }
    __syncthreads();

    int q  = t & 15;          // owns cols {2q, 2q+1, 32+2q, 32+2q+1}
    int n0 = (t >> 4) * 8;    // 8 consecutive rows

    unsigned long long acc[16];
#pragma unroll
    for (int i = 0; i < 16; i++) acc[i] = 0ull;

#pragma unroll 8
    for (int k = 0; k < 64; k++) {
        float2 wrA = *(const float2*)(sWr + k * 64 + 2 * q);
        float2 wrB = *(const float2*)(sWr + k * 64 + 32 + 2 * q);
        float2 wsA = *(const float2*)(sWs + k * 64 + 2 * q);
        float2 wsB = *(const float2*)(sWs + k * 64 + 32 + 2 * q);
        unsigned long long wrA0, wrA1, wrB0, wrB1, wsA0, wsA1, wsB0, wsB1;
        PACK2(wrA0, wrA.x); PACK2(wrA1, wrA.y);
        PACK2(wrB0, wrB.x); PACK2(wrB1, wrB.y);
        PACK2(wsA0, wsA.x); PACK2(wsA1, wsA.y);
        PACK2(wsB0, wsB.x); PACK2(wsB1, wsB.y);

        ulonglong2 a01 = *(const ulonglong2*)(sAt + k * 132 + n0);
        ulonglong2 a23 = *(const ulonglong2*)(sAt + k * 132 + n0 + 4);
        ulonglong2 x01 = *(const ulonglong2*)(sXt + k * 132 + n0);
        ulonglong2 x23 = *(const ulonglong2*)(sXt + k * 132 + n0 + 4);

        FMA2(acc[0],  a01.x, wrA0); FMA2(acc[0],  x01.x, wsA0);
        FMA2(acc[1],  a01.x, wrA1); FMA2(acc[1],  x01.x, wsA1);
        FMA2(acc[2],  a01.x, wrB0); FMA2(acc[2],  x01.x, wsB0);
        FMA2(acc[3],  a01.x, wrB1); FMA2(acc[3],  x01.x, wsB1);

        FMA2(acc[4],  a01.y, wrA0); FMA2(acc[4],  x01.y, wsA0);
        FMA2(acc[5],  a01.y, wrA1); FMA2(acc[5],  x01.y, wsA1);
        FMA2(acc[6],  a01.y, wrB0); FMA2(acc[6],  x01.y, wsB0);
        FMA2(acc[7],  a01.y, wrB1); FMA2(acc[7],  x01.y, wsB1);

        FMA2(acc[8],  a23.x, wrA0); FMA2(acc[8],  x23.x, wsA0);
        FMA2(acc[9],  a23.x, wrA1); FMA2(acc[9],  x23.x, wsA1);
        FMA2(acc[10], a23.x, wrB0); FMA2(acc[10], x23.x, wsB0);
        FMA2(acc[11], a23.x, wrB1); FMA2(acc[11], x23.x, wsB1);

        FMA2(acc[12], a23.y, wrA0); FMA2(acc[12], x23.y, wsA0);
        FMA2(acc[13], a23.y, wrA1); FMA2(acc[13], x23.y, wsA1);
        FMA2(acc[14], a23.y, wrB0); FMA2(acc[14], x23.y, wsB0);
        FMA2(acc[15], a23.y, wrB1); FMA2(acc[15], x23.y, wsB1);
    }

    int cA = 2 * q;
    int cB = 32 + 2 * q;
    float bA0 = br[cA], bA1 = br[cA + 1], bB0 = br[cB], bB1 = br[cB + 1];

#pragma unroll
    for (int rp = 0; rp < 4; rp++) {
        float vA0lo, vA0hi, vA1lo, vA1hi, vB0lo, vB0hi, vB1lo, vB1hi;
        UNPK(vA0lo, vA0hi, acc[rp * 4 + 0]);
        UNPK(vA1lo, vA1hi, acc[rp * 4 + 1]);
        UNPK(vB0lo, vB0hi, acc[rp * 4 + 2]);
        UNPK(vB1lo, vB1hi, acc[rp * 4 + 3]);
        int rlo = n0g + n0 + 2 * rp;
        if (rlo < NN) {
            float2 oA = make_float2(fmaxf(vA0lo + bA0, 0.f), fmaxf(vA1lo + bA1, 0.f));
            float2 oB = make_float2(fmaxf(vB0lo + bB0, 0.f), fmaxf(vB1lo + bB1, 0.f));
            *(float2*)(out + (size_t)rlo * 64 + cA) = oA;
            *(float2*)(out + (size_t)rlo * 64 + cB) = oB;
        }
        if (rlo + 1 < NN) {
            float2 oA = make_float2(fmaxf(vA0hi + bA0, 0.f), fmaxf(vA1hi + bA1, 0.f));
            float2 oB = make_float2(fmaxf(vB0hi + bB0, 0.f), fmaxf(vB1hi + bB1, 0.f));
            *(float2*)(out + (size_t)(rlo + 1) * 64 + cA) = oA;
            *(float2*)(out + (size_t)(rlo + 1) * 64 + cB) = oB;
        }
    }
}

// ---------------- global add pool (batch is sorted -> ranges) ----------------
__device__ __forceinline__ int lower_bound_i(const int* __restrict__ a, int n, int v) {
    int lo = 0, hi = n;
    while (lo < hi) {
        int mid = (lo + hi) >> 1;
        if (a[mid] < v) lo = mid + 1; else hi = mid;
    }
    return lo;
}

__global__ void k_pool(const float* __restrict__ h, const int* __restrict__ batch) {
    __shared__ float red[512];
    int g = blockIdx.x, t = threadIdx.x;
    int c = t & 63, q = t >> 6;
    int start = lower_bound_i(batch, NN, g);
    int end   = lower_bound_i(batch, NN, g + 1);
    float acc = 0.f;
    for (int n = start + q; n < end; n += 8) acc += h[(size_t)n * 64 + c];
    red[t] = acc;
    __syncthreads();
    if (q < 4) red[t] += red[t + 256];
    __syncthreads();
    if (q < 2) red[t] += red[t + 128];
    __syncthreads();
    if (q == 0)
        g_pool[g * 64 + c] = red[c] + red[c + 64];
}

// ---------------- FC head + log_softmax ----------------
__global__ void k_fc(const float* __restrict__ W1, const float* __restrict__ b1,
                     const float* __restrict__ W2, const float* __restrict__ b2,
                     float* __restrict__ out) {
    __shared__ float sg[64], sh[64], sl[3];
    int g = blockIdx.x, t = threadIdx.x;
    sg[t] = g_pool[g * 64 + t];
    __syncthreads();
    float a = b1[t];
#pragma unroll 8
    for (int k = 0; k < 64; k++) a += sg[k] * W1[k * 64 + t];
    sh[t] = fmaxf(a, 0.f);
    __syncthreads();
    if (t < 3) {
        float l = b2[t];
        for (int k = 0; k < 64; k++) l += sh[k] * W2[k * 3 + t];
        sl[t] = l;
    }
    __syncthreads();
    if (t < 3) {
        float m = fmaxf(sl[0], fmaxf(sl[1], sl[2]));
        float s = expf(sl[0] - m) + expf(sl[1] - m) + expf(sl[2] - m);
        out[g * 3 + t] = sl[t] - m - logf(s);
    }
}

// ------------------------------- launcher -------------------------------
extern "C" void kernel_launch(void* const* d_in, const int* in_sizes, int n_in,
                              void* d_out, int out_size) {
    const float* x     = (const float*)d_in[0];
    const int*   ei    = (const int*)d_in[1];
    const int*   src   = ei;
    const int*   dst   = ei + NE;
    const int*   batch = (const int*)d_in[2];
    const float* Wr1 = (const float*)d_in[3];
    const float* br1 = (const float*)d_in[4];
    const float* Ws1 = (const float*)d_in[5];
    const float* Wr2 = (const float*)d_in[6];
    const float* br2 = (const float*)d_in[7];
    const float* Ws2 = (const float*)d_in[8];
    const float* Wr3 = (const float*)d_in[9];
    const float* br3 = (const float*)d_in[10];
    const float* Ws3 = (const float*)d_in[11];
    const float* Wf1 = (const float*)d_in[12];
    const float* bf1 = (const float*)d_in[13];
    const float* Wf2 = (const float*)d_in[14];
    const float* bf2 = (const float*)d_in[15];
    float* out = (float*)d_out;

    cudaFuncSetAttribute(k_layer, cudaFuncAttributeMaxDynamicSharedMemorySize, LAYER_SMEM);

    float *hA, *hB;
    int* degp;
    unsigned long long* pktp;
    cudaGetSymbolAddress((void**)&hA,   g_hA);
    cudaGetSymbolAddress((void**)&hB,   g_hB);
    cudaGetSymbolAddress((void**)&degp, g_deg);
    cudaGetSymbolAddress((void**)&pktp, g_scanpkt);

    // CSR build (counting sort by dst) — 3 kernels, so k_layer is launch #4
    cudaMemsetAsync(degp, 0, NN * sizeof(int));
    cudaMemsetAsync(pktp, 0, NCHUNK * sizeof(unsigned long long));
    k_hist<<<(NE + 255) / 256, 256>>>(dst);
    k_scan<<<NCHUNK, SCAN_CHUNK>>>();
    k_scatter<<<(NE + 255) / 256, 256>>>(src, dst);

    const int LAYER_GRID = (NN + 127) / 128;

    k_layer<<<LAYER_GRID, 256, LAYER_SMEM>>>(x,  Wr1, Ws1, br1, hA);
    k_layer<<<LAYER_GRID, 256, LAYER_SMEM>>>(hA, Wr2, Ws2, br2, hB);
    k_layer<<<LAYER_GRID, 256, LAYER_SMEM>>>(hB, Wr3, Ws3, br3, hA);

    k_pool<<<NG, 512>>>(hA, batch);
    k_fc<<<NG, 64>>>(Wf1, bf1, Wf2, bf2, out);
}